// round 8
// baseline (speedup 1.0000x reference)
#include <cuda_runtime.h>
#include <math.h>
#include <stdint.h>

#define NEURONS 54
#define NPAD    64
#define DT      4
#define STEPS   30
#define BATCHES 128
#define KDIM    5625      // 75*75
#define KC      128       // K chunk for FC
#define NKC     44        // ceil(5625/128)
#define CL      8         // cluster size for glm
#define CTHREADS 128
#define WARPS_TOT 32      // CL * 4 warps

// scratch (zero-initialized device global; pad neurons never written -> stay 0)
__device__ float g_fcpart[NKC * BATCHES * NPAD];    // [kc][b][n]

__device__ __forceinline__ uint32_t smem_u32(const void* p) {
    uint32_t a;
    asm("{ .reg .u64 t; cvta.to.shared.u64 t, %1; cvt.u32.u64 %0, t; }"
        : "=r"(a) : "l"(p));
    return a;
}

// ---------------------------------------------------------------------------
// Kernel 1: FUSED 8x8 avg-pool + split-K FC.
// grid = (44 k-chunks, 16 batch-tiles of 8), 256 threads (8 warps).
// Warp w owns batch bt*8+w: lanes stream-pool 4 k-values each (16 __ldcs
// float4 per value, coalesced), stash to smem, then dot with the staged
// 54x128 fc_w chunk (one LDS.128 + 4 FMA + 5 shfl per neuron).
// ---------------------------------------------------------------------------
__global__ void __launch_bounds__(256) poolfc_kernel(
    const float* __restrict__ x, const float* __restrict__ fc_w)
{
    __shared__ __align__(16) float Ws[NEURONS * KC];
    __shared__ __align__(16) float P[8][KC];

    const int kc  = blockIdx.x;          // 0..43
    const int bt  = blockIdx.y;          // 0..15
    const int tid = threadIdx.x;
    const int lane = tid & 31, w = tid >> 5;
    const int k0  = kc * KC;
    const int b   = bt * 8 + w;

    // stage fc_w chunk (L2-resident after first wave)
    for (int i = tid; i < NEURONS * KC; i += 256) {
        int n = i / KC, k = i - n * KC;
        int kg = k0 + k;
        Ws[i] = (kg < KDIM) ? fc_w[n * KDIM + kg] : 0.f;
    }

    // streaming pool: 4 pooled values per thread
    float pv[4];
#pragma unroll
    for (int s = 0; s < 4; s++) {
        const int k = k0 + lane + 32 * s;
        float sum = 0.f;
        if (k < KDIM) {
            int rg = k / 75, p = k - rg * 75;
            const float4* xp = (const float4*)x + ((b * 600 + rg * 8) * 150 + p * 2);
#pragma unroll
            for (int rr = 0; rr < 8; rr++) {
                float4 a = __ldcs(xp + rr * 150);
                float4 c = __ldcs(xp + rr * 150 + 1);
                sum += (a.x + a.y) + (a.z + a.w) + (c.x + c.y) + (c.z + c.w);
            }
        }
        pv[s] = sum * (1.f / 64.f);
    }
#pragma unroll
    for (int s = 0; s < 4; s++) P[w][lane + 32 * s] = pv[s];
    __syncthreads();

    // dot: warp w = batch b, 54 neurons over the 128-k chunk
    const float4 p4 = ((const float4*)P[w])[lane];
    const float4* W4 = (const float4*)Ws;
    float* dst = &g_fcpart[(kc * BATCHES + b) * NPAD];
    for (int n = 0; n < NEURONS; n++) {
        float4 wv = W4[n * 32 + lane];
        float a = p4.x * wv.x + p4.y * wv.y + p4.z * wv.z + p4.w * wv.w;
#pragma unroll
        for (int d = 16; d; d >>= 1) a += __shfl_xor_sync(0xffffffffu, a, d);
        if (lane == 0) dst[n] = a;
    }
}

// ---------------------------------------------------------------------------
// Kernel 2: 30-step GLM scan over an 8-CTA CLUSTER (8 SMs). (R6 version —
// barrier.cluster sync, proven correct/fast.)
// Prologue: fused reduce(44 fc partials)+bias+exp -> exf.
// Per step: dual 3-level shfl reduce (S_b, T_b) -> eS=__expf(S_b) ->
// rb=eS*T_b -> 2-level shfl -> lane0 multicasts warp partial to all 8 CTAs
// -> cluster arrive -> [shadow: prefetch BOTH next LUT candidates,
// premultiplied] -> cluster wait -> local sum of 32 partials -> thr.
// ---------------------------------------------------------------------------
__global__ void __launch_bounds__(CTHREADS, 1) __cluster_dims__(CL, 1, 1)
glm_kernel(const float* __restrict__ lw, const float* __restrict__ hw,
           const float* __restrict__ fc_b, float* __restrict__ out)
{
    __shared__ float2 lut[NPAD * 18];                 // {hs, exp(h-hs)}
    __shared__ __align__(16) float gat[2][WARPS_TOT]; // [parity][global warp]

    const int tid = threadIdx.x;
    const int lane = tid & 31, wid = tid >> 5;
    uint32_t rank;
    asm("mov.u32 %0, %%cluster_ctarank;" : "=r"(rank));
    const int gwid = (int)rank * 4 + wid;

    const int b = (int)rank * 16 + (tid >> 3);
    const int g = tid & 7;

    // fused reduce of fc partials (long-latency LDGs issued first)
    float acc[8];
#pragma unroll
    for (int i = 0; i < 8; i++) acc[i] = 0.f;
#pragma unroll 4
    for (int kc = 0; kc < NKC; kc++) {
        const float* p = &g_fcpart[(kc * BATCHES + b) * NPAD + g];
#pragma unroll
        for (int i = 0; i < 8; i++) acc[i] += p[8 * i];
    }

    // build LUT: 1024 entries / 128 threads (overlaps with LDGs above)
    for (int e = tid; e < NPAD * 16; e += CTHREADS) {
        int n = e >> 4, nib = e & 15;
        float hs = 0.f, h = 0.f;
        if (n < NEURONS) {
#pragma unroll
            for (int t = 0; t < DT; t++)
                if (nib & (1 << t)) { hs += lw[n * DT + t]; h += hw[t]; }
        }
        lut[n * 18 + nib] = make_float2(hs, expf(h - hs));
    }

    float exf[8];
#pragma unroll
    for (int i = 0; i < 8; i++) {
        const int n = g + 8 * i;
        exf[i] = (n < NEURONS) ? expf(acc[i] + fc_b[n]) : 0.f;
    }

    // remote addresses of my gat slot (buffer 0) in every CTA
    uint32_t rem[CL];
    {
        uint32_t base = smem_u32(&gat[0][0]) + (uint32_t)gwid * 4u;
#pragma unroll
        for (int r = 0; r < CL; r++)
            asm("mapa.shared::cluster.u32 %0, %1, %2;"
                : "=r"(rem[r]) : "r"(base), "r"(r));
    }

    __syncthreads();
    asm volatile("barrier.cluster.arrive.aligned;" ::: "memory");
    asm volatile("barrier.cluster.wait.aligned;"   ::: "memory");

    // state: pe[i] = exf*er(cur nib), slS = sum hs(cur nib); history all-zero
    unsigned nibs = 0;
    float slS = 0.f;
    float pe[8], cnt[8];
#pragma unroll
    for (int i = 0; i < 8; i++) { pe[i] = exf[i]; cnt[i] = 0.f; }

    for (int step = 0; step < STEPS; step++) {
        float sv = slS, tv = 0.f;
#pragma unroll
        for (int i = 0; i < 8; i++) tv += pe[i];

        // dual per-batch reduce over the 8 g-lanes
#pragma unroll
        for (int d = 1; d <= 4; d <<= 1) {
            sv += __shfl_xor_sync(0xffffffffu, sv, d);
            tv += __shfl_xor_sync(0xffffffffu, tv, d);
        }
        const float eS = __expf(sv);
        float rs = eS * tv;                      // batch rate-sum
        rs += __shfl_xor_sync(0xffffffffu, rs, 8);
        rs += __shfl_xor_sync(0xffffffffu, rs, 16);

        const uint32_t par_off = (step & 1) ? (WARPS_TOT * 4u) : 0u;
        if (lane == 0) {
#pragma unroll
            for (int r = 0; r < CL; r++)
                asm volatile("st.shared::cluster.f32 [%0], %1;"
                             :: "r"(rem[r] + par_off), "f"(rs) : "memory");
        }
        asm volatile("barrier.cluster.arrive.aligned;" ::: "memory");

        // --- barrier shadow: both next-LUT candidates, premultiplied ---
        float p0[8], p1[8], x0[8], x1[8];
#pragma unroll
        for (int i = 0; i < 8; i++) {
            unsigned nb = ((nibs >> (4 * i)) >> 1) & 7u;
            const float2* basep = &lut[(g + 8 * i) * 18];
            float2 a0 = basep[nb];        // no spike
            float2 a1 = basep[nb | 8u];   // spike
            x0[i] = a0.x; x1[i] = a1.x;
            p0[i] = exf[i] * a0.y; p1[i] = exf[i] * a1.y;
        }

        asm volatile("barrier.cluster.wait.aligned;" ::: "memory");

        // redundant local sum of 32 warp partials
        const float4* gp = (const float4*)&gat[step & 1][0];
        float t0 = 0.f, t1 = 0.f;
#pragma unroll
        for (int q = 0; q < 8; q += 2) {
            float4 v0 = gp[q], v1 = gp[q + 1];
            t0 += (v0.x + v0.y) + (v0.z + v0.w);
            t1 += (v1.x + v1.y) + (v1.z + v1.w);
        }
        const float thr = (t0 + t1) * (1.f / (BATCHES * NEURONS));

        unsigned nn = 0;
        slS = 0.f;
#pragma unroll
        for (int i = 0; i < 8; i++) {
            unsigned nib = (nibs >> (4 * i)) & 15u;
            bool sp = pe[i] * eS > thr;
            cnt[i] += sp ? 1.f : 0.f;
            pe[i]  = sp ? p1[i] : p0[i];
            slS   += sp ? x1[i] : x0[i];
            nn |= (((nib >> 1) | (sp ? 8u : 0u)) & 15u) << (4 * i);
        }
        nibs = nn;
    }

    // softplus(count), stable (count >= 0)
#pragma unroll
    for (int i = 0; i < 8; i++) {
        int n = g + 8 * i;
        if (n < NEURONS) {
            float c = cnt[i];
            out[b * NEURONS + n] = c + log1pf(expf(-c));
        }
    }
}

extern "C" void kernel_launch(void* const* d_in, const int* in_sizes, int n_in,
                              void* d_out, int out_size)
{
    const float* x   = (const float*)d_in[0];  // [128,1,600,600]
    const float* lw  = (const float*)d_in[1];  // [54,4]
    const float* hw  = (const float*)d_in[2];  // [4]
    const float* fcw = (const float*)d_in[3];  // [54,5625]
    const float* fcb = (const float*)d_in[4];  // [54]
    float* out = (float*)d_out;                // [128,54]

    poolfc_kernel<<<dim3(NKC, 16), 256>>>(x, fcw);
    glm_kernel<<<CL, CTHREADS>>>(lw, hw, fcb, out);
}